// round 2
// baseline (speedup 1.0000x reference)
#include <cuda_runtime.h>
#include <math_constants.h>
#include <cstddef>
#include <climits>

#define Bq   8
#define Np   4096
#define KK   20
#define EMBD 1024
#define ZDIM 256
#define MC   16
#define BNp  (Bq*Np)       // 32768
#define BNKp (BNp*KK)      // 655360
#define SLOPE  0.2f
#define BNEPS  1e-5f

// ---- small static scratch (~38 MB total) ----
__device__ int   g_idx[BNKp];            // 2.6 MB
__device__ float g_P [BNp*64];           // 8.4 MB
__device__ float g_Q [BNp*64];           // 8.4 MB
__device__ float g_mx[BNp*64];           // 8.4 MB
__device__ float g_mn[BNp*64];           // 8.4 MB
__device__ float g_psum[128*1024];       // 0.5 MB (reused by all stats stages)
__device__ float g_psq [128*1024];
__device__ float g_pmax[128*1024];
__device__ float g_pmin[128*1024];
__device__ float g_scale[64];
__device__ float g_bias [64];
__device__ float g_xglob[Bq*EMBD];
__device__ float g_z[Bq*ZDIM];

// output layout: flattened tuple (x_per^T [8,128,4096], xc [8,128,16], z [8,256,1], mu, log_var)
static const size_t OFF_XPER = 0;
static const size_t OFF_XC   = (size_t)Bq*128*Np;
static const size_t OFF_Z    = OFF_XC + (size_t)Bq*128*MC;
static const size_t OFF_MU   = OFF_Z  + (size_t)Bq*ZDIM;
static const size_t OFF_LV   = OFF_MU + (size_t)Bq*ZDIM;

__device__ __forceinline__ float lrelu(float v) { return v > 0.f ? v : SLOPE*v; }

// ---------------- kNN: block per query; cached per-thread argmax -------------
__global__ void knn_kernel(const float* __restrict__ pc)
{
    __shared__ float dist[Np];
    __shared__ float swv[8];
    __shared__ int   swi[8];
    __shared__ int   s_win;
    int bn = blockIdx.x;
    int b = bn >> 12, n = bn & (Np-1);
    int tid = threadIdx.x, lane = tid & 31, wid = tid >> 5;
    const float* base = pc + (size_t)b*Np*3;
    float qx = base[n*3+0], qy = base[n*3+1], qz = base[n*3+2];
    float qq = qx*qx + qy*qy + qz*qz;
    #pragma unroll
    for (int s = 0; s < 16; s++) {
        int j = tid + s*256;
        float px = base[j*3+0], py = base[j*3+1], pz = base[j*3+2];
        dist[j] = 2.f*(qx*px + qy*py + qz*pz) - qq - (px*px + py*py + pz*pz);
    }
    __syncthreads();
    // per-thread cached strip max (strip = {tid + 256*s})
    float bv = -CUDART_INF_F; int bi = INT_MAX;
    #pragma unroll
    for (int s = 0; s < 16; s++) {
        int j = tid + s*256;
        float v = dist[j];
        if (v > bv || (v == bv && j < bi)) { bv = v; bi = j; }
    }
    for (int r = 0; r < KK; r++) {
        float wv = bv; int wi = bi;
        #pragma unroll
        for (int off = 16; off > 0; off >>= 1) {
            float v2 = __shfl_down_sync(0xffffffffu, wv, off);
            int   i2 = __shfl_down_sync(0xffffffffu, wi, off);
            if (v2 > wv || (v2 == wv && i2 < wi)) { wv = v2; wi = i2; }
        }
        if (lane == 0) { swv[wid] = wv; swi[wid] = wi; }
        __syncthreads();
        if (tid == 0) {
            float gv = swv[0]; int gi = swi[0];
            #pragma unroll
            for (int w = 1; w < 8; w++) {
                float v2 = swv[w]; int i2 = swi[w];
                if (v2 > gv || (v2 == gv && i2 < gi)) { gv = v2; gi = i2; }
            }
            g_idx[bn*KK + r] = gi;
            dist[gi] = -CUDART_INF_F;
            s_win = gi;
        }
        __syncthreads();
        if ((s_win & 255) == tid) {          // only the losing strip rescans
            bv = -CUDART_INF_F; bi = INT_MAX;
            #pragma unroll
            for (int s = 0; s < 16; s++) {
                int j = tid + s*256;
                float v = dist[j];
                if (v > bv || (v == bv && j < bi)) { bv = v; bi = j; }
            }
        }
    }
}

// ---------------- stats of conv1a output (no materialization) -----------------
__global__ void stats1a_kernel(const float* __restrict__ pc, const float* __restrict__ W1a)
{
    __shared__ float rs[4][64], rq[4][64];
    int tid = threadIdx.x, o = tid & 63, g = tid >> 6;
    float wa[6];
    #pragma unroll
    for (int c = 0; c < 6; c++) wa[c] = W1a[o*6 + c];
    float s = 0.f, q = 0.f;
    int e0 = blockIdx.x*1024 + g*256;
    for (int i = 0; i < 256; i++) {
        int e = e0 + i;
        int p = e / KK;
        int n = p & (Np-1), b = p >> 12;
        int j = g_idx[e];
        const float* bb = pc + (size_t)b*Np*3;
        float cx = bb[n*3+0], cy = bb[n*3+1], cz = bb[n*3+2];
        float jx = bb[j*3+0], jy = bb[j*3+1], jz = bb[j*3+2];
        float h = wa[0]*(jx-cx) + wa[1]*(jy-cy) + wa[2]*(jz-cz)
                + wa[3]*cx + wa[4]*cy + wa[5]*cz;
        s += h; q += h*h;
    }
    rs[g][o] = s; rq[g][o] = q;
    __syncthreads();
    if (g == 0) {
        g_psum[blockIdx.x*64 + o] = rs[0][o]+rs[1][o]+rs[2][o]+rs[3][o];
        g_psq [blockIdx.x*64 + o] = rq[0][o]+rq[1][o]+rq[2][o]+rq[3][o];
    }
}

// ---------------- fold stats -> scale/bias (64 channels) ----------------------
__global__ void reduce_stats(int nb, float n,
                             const float* __restrict__ gamma, const float* __restrict__ beta)
{
    int ch = blockIdx.x, tid = threadIdx.x;
    __shared__ float ss[256], sq[256];
    float s = 0.f, q = 0.f;
    for (int i = tid; i < nb; i += 256) { s += g_psum[i*64+ch]; q += g_psq[i*64+ch]; }
    ss[tid] = s; sq[tid] = q;
    __syncthreads();
    for (int st = 128; st > 0; st >>= 1) {
        if (tid < st) { ss[tid] += ss[tid+st]; sq[tid] += sq[tid+st]; }
        __syncthreads();
    }
    if (tid == 0) {
        float mean = ss[0]/n;
        float var  = sq[0]/n - mean*mean;
        float rs   = rsqrtf(var + BNEPS);
        float sc   = gamma[ch]*rs;
        g_scale[ch] = sc;
        g_bias [ch] = beta[ch] - mean*sc;
    }
}

// ---------------- fused: recompute conv1a, BN+lrelu, conv1b, stats, max/min ---
__global__ void __launch_bounds__(256, 2)
conv1b_kernel(const float* __restrict__ pc, const float* __restrict__ W1a,
              const float* __restrict__ W1b)
{
    __shared__ float sx[4][KK][64];
    __shared__ float rs[4][64], rq[4][64];
    int tid = threadIdx.x, o = tid & 63, g = tid >> 6;
    float wa[6];
    #pragma unroll
    for (int c = 0; c < 6; c++) wa[c] = W1a[o*6 + c];
    float sc = g_scale[o], bs = g_bias[o];
    float wb[64];
    #pragma unroll
    for (int c = 0; c < 64; c++) wb[c] = W1b[o*64 + c];
    float s = 0.f, q = 0.f;
    int p0 = blockIdx.x*32 + g*8;
    for (int i = 0; i < 8; i++) {
        int p = p0 + i;
        int n = p & (Np-1), b = p >> 12;
        const float* bb = pc + (size_t)b*Np*3;
        float cx = bb[n*3+0], cy = bb[n*3+1], cz = bb[n*3+2];
        #pragma unroll
        for (int k = 0; k < KK; k++) {
            int j = g_idx[p*KK + k];
            float jx = bb[j*3+0], jy = bb[j*3+1], jz = bb[j*3+2];
            float h = wa[0]*(jx-cx) + wa[1]*(jy-cy) + wa[2]*(jz-cz)
                    + wa[3]*cx + wa[4]*cy + wa[5]*cz;
            sx[g][k][o] = lrelu(h*sc + bs);
        }
        __syncthreads();
        float mx = -CUDART_INF_F, mn = CUDART_INF_F;
        #pragma unroll
        for (int k = 0; k < KK; k++) {
            float a0=0.f, a1=0.f, a2=0.f, a3=0.f;
            const float4* xv = (const float4*)sx[g][k];
            #pragma unroll
            for (int c4 = 0; c4 < 16; c4++) {
                float4 v = xv[c4];
                a0 += wb[c4*4+0]*v.x; a1 += wb[c4*4+1]*v.y;
                a2 += wb[c4*4+2]*v.z; a3 += wb[c4*4+3]*v.w;
            }
            float h = (a0+a1)+(a2+a3);
            s += h; q += h*h; mx = fmaxf(mx, h); mn = fminf(mn, h);
        }
        g_mx[(size_t)p*64 + o] = mx;
        g_mn[(size_t)p*64 + o] = mn;
        __syncthreads();
    }
    rs[g][o] = s; rq[g][o] = q;
    __syncthreads();
    if (g == 0) {
        g_psum[blockIdx.x*64 + o] = rs[0][o]+rs[1][o]+rs[2][o]+rs[3][o];
        g_psq [blockIdx.x*64 + o] = rq[0][o]+rq[1][o]+rq[2][o]+rq[3][o];
    }
}

// ---------------- apply BN+lrelu to max-or-min (sign select), write x_per -----
__global__ void apply_kernel(float* __restrict__ out_xper, int choff)
{
    int bc = blockIdx.x;                 // b*64 + ch
    int b = bc >> 6, ch = bc & 63;
    float sc = g_scale[ch], bs = g_bias[ch];
    const float* src = (sc >= 0.f ? g_mx : g_mn);
    size_t obase = ((size_t)b*128 + choff + ch)*Np;
    for (int it = 0; it < 16; it++) {
        int n = it*256 + threadIdx.x;
        float v = src[(size_t)(b*Np + n)*64 + ch];
        out_xper[obase + n] = lrelu(v*sc + bs);
    }
}

// ---------------- P = Wd*x1, Q = (Wc-Wd)*x1 (x1 read back from out) ----------
__global__ void __launch_bounds__(256, 1)
pq_kernel(const float* __restrict__ out_xper, const float* __restrict__ W2a)
{
    __shared__ float sx[128*68];         // [pt][c], pad 4
    int tid = threadIdx.x, o = tid & 63, g = tid >> 6;
    int blk = blockIdx.x;                // 256 blocks of 128 points
    int b = blk >> 5, n0 = (blk & 31)*128;
    int pbase = blk*128;
    float wd[64], wq[64];
    #pragma unroll
    for (int c = 0; c < 64; c++) {
        float d = W2a[o*128 + c];
        wd[c] = d;
        wq[c] = W2a[o*128 + 64 + c] - d;
    }
    #pragma unroll
    for (int r = 0; r < 32; r++) {       // stage 128x64 from out (channel-major)
        int idx = r*256 + tid;
        int c = idx >> 7, i = idx & 127;
        sx[i*68 + c] = out_xper[((size_t)b*128 + c)*Np + n0 + i];
    }
    __syncthreads();
    for (int pt = 0; pt < 32; pt++) {
        int row = g*32 + pt;
        const float4* xv = (const float4*)&sx[row*68];
        float p0=0.f,p1=0.f,p2=0.f,p3=0.f, q0=0.f,q1=0.f,q2=0.f,q3=0.f;
        #pragma unroll
        for (int c4 = 0; c4 < 16; c4++) {
            float4 v = xv[c4];
            p0 += wd[c4*4+0]*v.x; p1 += wd[c4*4+1]*v.y;
            p2 += wd[c4*4+2]*v.z; p3 += wd[c4*4+3]*v.w;
            q0 += wq[c4*4+0]*v.x; q1 += wq[c4*4+1]*v.y;
            q2 += wq[c4*4+2]*v.z; q3 += wq[c4*4+3]*v.w;
        }
        g_P[(size_t)(pbase+row)*64 + o] = (p0+p1)+(p2+p3);
        g_Q[(size_t)(pbase+row)*64 + o] = (q0+q1)+(q2+q3);
    }
}

// ---------------- stats of conv2a output P[j]+Q[n] ----------------------------
__global__ void stats2a_kernel()
{
    __shared__ float rs[4][64], rq[4][64];
    int tid = threadIdx.x, o = tid & 63, g = tid >> 6;
    float s = 0.f, q = 0.f;
    int e0 = blockIdx.x*1024 + g*256;
    for (int i = 0; i < 256; i++) {
        int e = e0 + i;
        int p = e / KK;
        int b = p >> 12;
        int j = g_idx[e];
        float v = g_P[(size_t)((b<<12) + j)*64 + o] + g_Q[(size_t)p*64 + o];
        s += v; q += v*v;
    }
    rs[g][o] = s; rq[g][o] = q;
    __syncthreads();
    if (g == 0) {
        g_psum[blockIdx.x*64 + o] = rs[0][o]+rs[1][o]+rs[2][o]+rs[3][o];
        g_psq [blockIdx.x*64 + o] = rq[0][o]+rq[1][o]+rq[2][o]+rq[3][o];
    }
}

// ---------------- fused conv2b: gather P+Q, BN+lrelu, 64x64, stats, max/min ---
__global__ void __launch_bounds__(256, 2)
conv2b_kernel(const float* __restrict__ W2b)
{
    __shared__ float sx[4][KK][64];
    __shared__ float rs[4][64], rq[4][64];
    int tid = threadIdx.x, o = tid & 63, g = tid >> 6;
    float sc = g_scale[o], bs = g_bias[o];
    float wb[64];
    #pragma unroll
    for (int c = 0; c < 64; c++) wb[c] = W2b[o*64 + c];
    float s = 0.f, q = 0.f;
    int p0 = blockIdx.x*32 + g*8;
    for (int i = 0; i < 8; i++) {
        int p = p0 + i;
        int b = p >> 12;
        float qv = g_Q[(size_t)p*64 + o];
        #pragma unroll
        for (int k = 0; k < KK; k++) {
            int j = g_idx[p*KK + k];
            float v = g_P[(size_t)((b<<12) + j)*64 + o] + qv;
            sx[g][k][o] = lrelu(v*sc + bs);
        }
        __syncthreads();
        float mx = -CUDART_INF_F, mn = CUDART_INF_F;
        #pragma unroll
        for (int k = 0; k < KK; k++) {
            float a0=0.f, a1=0.f, a2=0.f, a3=0.f;
            const float4* xv = (const float4*)sx[g][k];
            #pragma unroll
            for (int c4 = 0; c4 < 16; c4++) {
                float4 v = xv[c4];
                a0 += wb[c4*4+0]*v.x; a1 += wb[c4*4+1]*v.y;
                a2 += wb[c4*4+2]*v.z; a3 += wb[c4*4+3]*v.w;
            }
            float h = (a0+a1)+(a2+a3);
            s += h; q += h*h; mx = fmaxf(mx, h); mn = fminf(mn, h);
        }
        g_mx[(size_t)p*64 + o] = mx;
        g_mn[(size_t)p*64 + o] = mn;
        __syncthreads();
    }
    rs[g][o] = s; rq[g][o] = q;
    __syncthreads();
    if (g == 0) {
        g_psum[blockIdx.x*64 + o] = rs[0][o]+rs[1][o]+rs[2][o]+rs[3][o];
        g_psq [blockIdx.x*64 + o] = rq[0][o]+rq[1][o]+rq[2][o]+rq[3][o];
    }
}

// ---------------- conv3 fused with stats + per-tile channel max/min -----------
__global__ void __launch_bounds__(256, 1)
conv3_kernel(const float* __restrict__ out_xper, const float* __restrict__ W3)
{
    __shared__ float sx[64*132];         // [pt][c], 128 c + 4 pad
    int tid = threadIdx.x, o = tid & 63, g = tid >> 6;
    int t = blockIdx.x;                  // point tile (256 points)
    int b = t >> 4, n0 = (t & 15)*256;
    int ob = blockIdx.y*64;
    float w[128];
    #pragma unroll
    for (int c = 0; c < 128; c++) w[c] = W3[(size_t)(ob+o)*128 + c];
    float s = 0.f, q = 0.f, mx = -CUDART_INF_F, mn = CUDART_INF_F;
    for (int st = 0; st < 4; st++) {
        __syncthreads();
        #pragma unroll
        for (int r = 0; r < 32; r++) {
            int idx = r*256 + tid;
            int c = idx >> 6, i = idx & 63;
            sx[i*132 + c] = out_xper[((size_t)b*128 + c)*Np + n0 + st*64 + i];
        }
        __syncthreads();
        for (int pt = 0; pt < 16; pt++) {
            const float4* xv = (const float4*)&sx[(g*16 + pt)*132];
            float a0=0.f, a1=0.f, a2=0.f, a3=0.f;
            #pragma unroll
            for (int c4 = 0; c4 < 32; c4++) {
                float4 v = xv[c4];
                a0 += w[c4*4+0]*v.x; a1 += w[c4*4+1]*v.y;
                a2 += w[c4*4+2]*v.z; a3 += w[c4*4+3]*v.w;
            }
            float h = (a0+a1)+(a2+a3);
            s += h; q += h*h; mx = fmaxf(mx, h); mn = fminf(mn, h);
        }
    }
    __syncthreads();
    float* red = sx;                     // reuse shared
    red[tid] = s; red[256+tid] = q; red[512+tid] = mx; red[768+tid] = mn;
    __syncthreads();
    if (g == 0) {
        float S  = red[o]     + red[64+o]     + red[128+o]     + red[192+o];
        float Qq = red[256+o] + red[320+o]    + red[384+o]     + red[448+o];
        float MX = fmaxf(fmaxf(red[512+o], red[576+o]), fmaxf(red[640+o], red[704+o]));
        float MN = fminf(fminf(red[768+o], red[832+o]), fminf(red[896+o], red[960+o]));
        int pi = t*1024 + ob + o;
        g_psum[pi] = S; g_psq[pi] = Qq; g_pmax[pi] = MX; g_pmin[pi] = MN;
    }
}

// ---------------- conv3 stats + batch max -> x_global -------------------------
__global__ void final3_kernel(const float* __restrict__ g3, const float* __restrict__ b3)
{
    int ch = blockIdx.x, tid = threadIdx.x;          // 1024 blocks x 128 threads
    __shared__ float ss[128], sq[128], smx[128], smn[128];
    __shared__ float s_sc, s_bs;
    ss[tid] = g_psum[tid*1024 + ch];
    sq[tid] = g_psq [tid*1024 + ch];
    __syncthreads();
    for (int st = 64; st > 0; st >>= 1) {
        if (tid < st) { ss[tid] += ss[tid+st]; sq[tid] += sq[tid+st]; }
        __syncthreads();
    }
    if (tid == 0) {
        float n = (float)BNp;
        float mean = ss[0]/n;
        float var  = sq[0]/n - mean*mean;
        float rs   = rsqrtf(var + BNEPS);
        float sc   = g3[ch]*rs;
        s_sc = sc; s_bs = b3[ch] - mean*sc;
    }
    smx[tid] = g_pmax[tid*1024 + ch];                // tid = b*16 + i
    smn[tid] = g_pmin[tid*1024 + ch];
    __syncthreads();
    #pragma unroll
    for (int st = 8; st > 0; st >>= 1) {
        if ((tid & 15) < st) {
            smx[tid] = fmaxf(smx[tid], smx[tid+st]);
            smn[tid] = fminf(smn[tid], smn[tid+st]);
        }
        __syncthreads();
    }
    if ((tid & 15) == 0) {
        int b = tid >> 4;
        float v = (s_sc >= 0.f) ? smx[tid] : smn[tid];
        g_xglob[b*EMBD + ch] = lrelu(v*s_sc + s_bs);
    }
}

// ---------------- heads: mu, log_var, z ---------------------------------------
__global__ void heads_kernel(const float* __restrict__ eps,
                             const float* __restrict__ Wmu, const float* __restrict__ bmu,
                             const float* __restrict__ Wvar, const float* __restrict__ bvar,
                             float* __restrict__ out)
{
    __shared__ float sg[EMBD];
    int b = blockIdx.x, tid = threadIdx.x;
    for (int i = tid; i < EMBD; i += 256) sg[i] = g_xglob[b*EMBD + i];
    __syncthreads();
    int z = tid;
    float mu = bmu[z], lv = bvar[z];
    const float4* wm  = (const float4*)(Wmu  + (size_t)z*EMBD);
    const float4* wv  = (const float4*)(Wvar + (size_t)z*EMBD);
    const float4* sg4 = (const float4*)sg;
    for (int c4 = 0; c4 < 256; c4++) {
        float4 gg = sg4[c4];
        float4 a  = wm[c4];
        float4 c  = wv[c4];
        mu += a.x*gg.x + a.y*gg.y + a.z*gg.z + a.w*gg.w;
        lv += c.x*gg.x + c.y*gg.y + c.z*gg.z + c.w*gg.w;
    }
    float zz = eps[b*ZDIM + z]*expf(0.5f*lv) + mu;
    out[OFF_MU + b*ZDIM + z] = mu;
    out[OFF_LV + b*ZDIM + z] = lv;
    out[OFF_Z  + b*ZDIM + z] = zz;
    g_z[b*ZDIM + z] = zz;
}

// ---------------- cuboid decoder ----------------------------------------------
__global__ void decoder_kernel(const float* __restrict__ Wenc,
                               const float* __restrict__ Wc1,
                               const float* __restrict__ Wc2,
                               float* __restrict__ out)
{
    __shared__ float s_z[ZDIM];
    __shared__ float s_enc[64*MC];
    __shared__ float s_h[256*MC];
    int b = blockIdx.x, tid = threadIdx.x;
    if (tid < ZDIM) s_z[tid] = g_z[b*ZDIM + tid];
    for (int i = tid; i < 64*MC; i += 256) s_enc[i] = lrelu(Wenc[i]);
    __syncthreads();
    {
        const float* w = Wc1 + (size_t)tid*320;
        float zdot = 0.f;
        for (int c = 0; c < 256; c++) zdot += w[c]*s_z[c];
        float a[MC];
        #pragma unroll
        for (int m = 0; m < MC; m++) a[m] = zdot;
        for (int c = 0; c < 64; c++) {
            float ww = w[256 + c];
            #pragma unroll
            for (int m = 0; m < MC; m++) a[m] += ww*s_enc[c*MC + m];
        }
        #pragma unroll
        for (int m = 0; m < MC; m++) s_h[tid*MC + m] = lrelu(a[m]);
    }
    __syncthreads();
    if (tid < 128) {
        const float* w = Wc2 + (size_t)tid*256;
        float a[MC];
        #pragma unroll
        for (int m = 0; m < MC; m++) a[m] = 0.f;
        for (int c = 0; c < 256; c++) {
            float ww = w[c];
            #pragma unroll
            for (int m = 0; m < MC; m++) a[m] += ww*s_h[c*MC + m];
        }
        #pragma unroll
        for (int m = 0; m < MC; m++)
            out[OFF_XC + ((size_t)b*128 + tid)*MC + m] = lrelu(a[m]);
    }
}

// ---------------- launch ------------------------------------------------------
extern "C" void kernel_launch(void* const* d_in, const int* in_sizes, int n_in,
                              void* d_out, int out_size)
{
    const float* pc   = (const float*)d_in[0];
    const float* eps  = (const float*)d_in[1];
    const float* W1a  = (const float*)d_in[2];
    const float* g1a  = (const float*)d_in[3];
    const float* b1a  = (const float*)d_in[4];
    const float* W1b  = (const float*)d_in[5];
    const float* g1b  = (const float*)d_in[6];
    const float* b1b  = (const float*)d_in[7];
    const float* W2a  = (const float*)d_in[8];
    const float* g2a  = (const float*)d_in[9];
    const float* b2a  = (const float*)d_in[10];
    const float* W2b  = (const float*)d_in[11];
    const float* g2b  = (const float*)d_in[12];
    const float* b2b  = (const float*)d_in[13];
    const float* W3   = (const float*)d_in[14];
    const float* g3   = (const float*)d_in[15];
    const float* b3   = (const float*)d_in[16];
    const float* Wmu  = (const float*)d_in[17];
    const float* bmu  = (const float*)d_in[18];
    const float* Wvar = (const float*)d_in[19];
    const float* bvar = (const float*)d_in[20];
    const float* Wenc = (const float*)d_in[21];
    const float* Wc1  = (const float*)d_in[22];
    const float* Wc2  = (const float*)d_in[23];
    float* out = (float*)d_out;

    knn_kernel<<<BNp, 256>>>(pc);

    // EdgeConv 1
    stats1a_kernel<<<640, 256>>>(pc, W1a);
    reduce_stats<<<64, 256>>>(640, (float)BNKp, g1a, b1a);
    conv1b_kernel<<<1024, 256>>>(pc, W1a, W1b);
    reduce_stats<<<64, 256>>>(1024, (float)BNKp, g1b, b1b);
    apply_kernel<<<512, 256>>>(out, 0);

    // EdgeConv 2 (factored: P[j] + Q[n])
    pq_kernel<<<256, 256>>>(out, W2a);
    stats2a_kernel<<<640, 256>>>();
    reduce_stats<<<64, 256>>>(640, (float)BNKp, g2a, b2a);
    conv2b_kernel<<<1024, 256>>>(W2b);
    reduce_stats<<<64, 256>>>(1024, (float)BNKp, g2b, b2b);
    apply_kernel<<<512, 256>>>(out, 64);

    // global feature
    conv3_kernel<<<dim3(128, 16), 256>>>(out, W3);
    final3_kernel<<<EMBD, 128>>>(g3, b3);

    // heads + decoder
    heads_kernel<<<Bq, 256>>>(eps, Wmu, bmu, Wvar, bvar, out);
    decoder_kernel<<<Bq, 256>>>(Wenc, Wc1, Wc2, out);
}